// round 3
// baseline (speedup 1.0000x reference)
#include <cuda_runtime.h>
#include <cuda_bf16.h>
#include <math.h>

#define NROWS 8192
#define NDIM  384
#define EPSV  1e-8f

#define BM 128
#define BN 128
#define BK 64
#define JSPLIT 4
#define TILES_PER_SPLIT (NROWS / (JSPLIT * BN))   // 16

// Scratch (static device memory; no allocations)
__device__ float g_x[(size_t)NROWS * NDIM];       // normalized rows
__device__ float g_pv[JSPLIT * NROWS];            // partial best value per split
__device__ int   g_pi[JSPLIT * NROWS];            // partial best index per split
__device__ float g_logd[NROWS];                   // per-row log distance

// ---------------------------------------------------------------------------
// Kernel 1: L2 normalize rows. One warp per row.
// ---------------------------------------------------------------------------
__global__ void koleo_normalize(const float* __restrict__ in) {
    int gwarp = (blockIdx.x * blockDim.x + threadIdx.x) >> 5;
    int lane = threadIdx.x & 31;
    if (gwarp >= NROWS) return;

    const float4* a4 = (const float4*)(in + (size_t)gwarp * NDIM);
    float4 v[3];
    float ss = 0.0f;
#pragma unroll
    for (int t = 0; t < 3; t++) {
        v[t] = a4[lane + 32 * t];
        ss = fmaf(v[t].x, v[t].x, ss);
        ss = fmaf(v[t].y, v[t].y, ss);
        ss = fmaf(v[t].z, v[t].z, ss);
        ss = fmaf(v[t].w, v[t].w, ss);
    }
#pragma unroll
    for (int o = 16; o > 0; o >>= 1)
        ss += __shfl_xor_sync(0xffffffffu, ss, o);

    float nrm = sqrtf(ss);
    float inv = 1.0f / fmaxf(nrm, EPSV);

    float4* o4 = (float4*)(g_x + (size_t)gwarp * NDIM);
#pragma unroll
    for (int t = 0; t < 3; t++) {
        float4 w;
        w.x = v[t].x * inv; w.y = v[t].y * inv;
        w.z = v[t].z * inv; w.w = v[t].w * inv;
        o4[lane + 32 * t] = w;
    }
}

// ---------------------------------------------------------------------------
// Kernel 2: tiled Gram-matrix with fused running argmax.
// grid = (NROWS/BM, JSPLIT); 256 threads; 8x8 micro-tile per thread.
// Smem tiles stored k-major: As[k][m], Bs[k][n]  (64 x 128 floats each).
// ---------------------------------------------------------------------------
__global__ void __launch_bounds__(256, 2) koleo_argmax(float* __restrict__ pv,
                                                       int* __restrict__ pi) {
    extern __shared__ float sm[];
    float* As = sm;              // BK * BM
    float* Bs = sm + BK * BM;    // BK * BN

    const int tid = threadIdx.x;
    const int tx = tid & 15;     // 0..15 -> column groups
    const int ty = tid >> 4;     // 0..15 -> row groups
    const int row0 = blockIdx.x * BM;
    const int sp = blockIdx.y;
    const int jt0 = sp * TILES_PER_SPLIT;

    const float4* x4 = (const float4*)g_x;

    float bestv[8];
    int   besti[8];
#pragma unroll
    for (int i = 0; i < 8; i++) { bestv[i] = -2.0f; besti[i] = 0; }

    for (int jt = jt0; jt < jt0 + TILES_PER_SPLIT; ++jt) {
        const int col0 = jt * BN;

        float acc[8][8];
#pragma unroll
        for (int i = 0; i < 8; i++)
#pragma unroll
            for (int j = 0; j < 8; j++) acc[i][j] = 0.0f;

#pragma unroll 1
        for (int kt = 0; kt < NDIM / BK; ++kt) {
            const int k4 = kt * (BK / 4);
            // Load A chunk (rows row0..+127, k-slice) transposed into As[k][m]
#pragma unroll
            for (int it = 0; it < 8; ++it) {
                int q = tid + it * 256;
                int r = q >> 4;          // 0..127
                int s = q & 15;          // float4 segment within 64 k's
                float4 v = x4[(size_t)(row0 + r) * (NDIM / 4) + k4 + s];
                int kk = s * 4;
                As[(kk + 0) * BM + r] = v.x;
                As[(kk + 1) * BM + r] = v.y;
                As[(kk + 2) * BM + r] = v.z;
                As[(kk + 3) * BM + r] = v.w;
            }
            // Load B chunk (rows col0..+127) transposed into Bs[k][n]
#pragma unroll
            for (int it = 0; it < 8; ++it) {
                int q = tid + it * 256;
                int r = q >> 4;
                int s = q & 15;
                float4 v = x4[(size_t)(col0 + r) * (NDIM / 4) + k4 + s];
                int kk = s * 4;
                Bs[(kk + 0) * BN + r] = v.x;
                Bs[(kk + 1) * BN + r] = v.y;
                Bs[(kk + 2) * BN + r] = v.z;
                Bs[(kk + 3) * BN + r] = v.w;
            }
            __syncthreads();

#pragma unroll
            for (int k = 0; k < BK; ++k) {
                float4 a0 = *(const float4*)&As[k * BM + ty * 4];
                float4 a1 = *(const float4*)&As[k * BM + 64 + ty * 4];
                float4 b0 = *(const float4*)&Bs[k * BN + tx * 4];
                float4 b1 = *(const float4*)&Bs[k * BN + 64 + tx * 4];
                float a[8] = {a0.x, a0.y, a0.z, a0.w, a1.x, a1.y, a1.z, a1.w};
                float b[8] = {b0.x, b0.y, b0.z, b0.w, b1.x, b1.y, b1.z, b1.w};
#pragma unroll
                for (int i = 0; i < 8; i++)
#pragma unroll
                    for (int j = 0; j < 8; j++)
                        acc[i][j] = fmaf(a[i], b[j], acc[i][j]);
            }
            __syncthreads();
        }

        // Fused epilogue: update running per-row argmax, skipping the diagonal.
#pragma unroll
        for (int i = 0; i < 8; i++) {
            int gi = row0 + ((i < 4) ? (ty * 4 + i) : (64 + ty * 4 + i - 4));
#pragma unroll
            for (int j = 0; j < 8; j++) {
                int gj = col0 + ((j < 4) ? (tx * 4 + j) : (64 + tx * 4 + j - 4));
                float v = acc[i][j];
                if (gi != gj &&
                    (v > bestv[i] || (v == bestv[i] && gj < besti[i]))) {
                    bestv[i] = v;
                    besti[i] = gj;
                }
            }
        }
    }

    // Cross-thread (tx) reduction per row via smem (reuse tile memory).
    __syncthreads();
    float* rv = sm;                       // 128*16 floats
    int* ri = (int*)(sm + BM * 16);       // 128*16 ints
#pragma unroll
    for (int i = 0; i < 8; i++) {
        int lr = (i < 4) ? (ty * 4 + i) : (64 + ty * 4 + i - 4);
        rv[lr * 16 + tx] = bestv[i];
        ri[lr * 16 + tx] = besti[i];
    }
    __syncthreads();
    if (tid < BM) {
        float bv = -2.0f; int bi = 0x7fffffff;
        for (int t = 0; t < 16; t++) {
            float v = rv[tid * 16 + t];
            int ix = ri[tid * 16 + t];
            if (v > bv || (v == bv && ix < bi)) { bv = v; bi = ix; }
        }
        pv[sp * NROWS + row0 + tid] = bv;
        pi[sp * NROWS + row0 + tid] = bi;
    }
}

// ---------------------------------------------------------------------------
// Kernel 3: merge split partials, compute log pairwise distance. Warp/row.
// ---------------------------------------------------------------------------
__global__ void koleo_dist() {
    int gwarp = (blockIdx.x * blockDim.x + threadIdx.x) >> 5;
    int lane = threadIdx.x & 31;
    if (gwarp >= NROWS) return;

    int bi = 0;
    if (lane == 0) {
        float bv = -2.0f; bi = 0x7fffffff;
        for (int s = 0; s < JSPLIT; s++) {
            float v = g_pv[s * NROWS + gwarp];
            int ix = g_pi[s * NROWS + gwarp];
            if (v > bv || (v == bv && ix < bi)) { bv = v; bi = ix; }
        }
    }
    bi = __shfl_sync(0xffffffffu, bi, 0);

    const float4* a4 = (const float4*)(g_x + (size_t)gwarp * NDIM);
    const float4* b4 = (const float4*)(g_x + (size_t)bi * NDIM);
    float ss = 0.0f;
#pragma unroll
    for (int t = 0; t < 3; t++) {
        float4 a = a4[lane + 32 * t];
        float4 b = b4[lane + 32 * t];
        float dx = a.x - b.x + EPSV;
        float dy = a.y - b.y + EPSV;
        float dz = a.z - b.z + EPSV;
        float dw = a.w - b.w + EPSV;
        ss = fmaf(dx, dx, ss);
        ss = fmaf(dy, dy, ss);
        ss = fmaf(dz, dz, ss);
        ss = fmaf(dw, dw, ss);
    }
#pragma unroll
    for (int o = 16; o > 0; o >>= 1)
        ss += __shfl_xor_sync(0xffffffffu, ss, o);

    if (lane == 0)
        g_logd[gwarp] = logf(sqrtf(ss) + EPSV);
}

// ---------------------------------------------------------------------------
// Kernel 4: deterministic reduction -> loss scalar.
// ---------------------------------------------------------------------------
__global__ void koleo_reduce(float* __restrict__ out) {
    __shared__ float s[256];
    float acc = 0.0f;
    for (int i = threadIdx.x; i < NROWS; i += 256) acc += g_logd[i];
    s[threadIdx.x] = acc;
    __syncthreads();
    for (int w = 128; w > 0; w >>= 1) {
        if (threadIdx.x < w) s[threadIdx.x] += s[threadIdx.x + w];
        __syncthreads();
    }
    if (threadIdx.x == 0) out[0] = -s[0] / (float)NROWS;
}

// ---------------------------------------------------------------------------
extern "C" void kernel_launch(void* const* d_in, const int* in_sizes, int n_in,
                              void* d_out, int out_size) {
    const float* in = (const float*)d_in[0];
    float* out = (float*)d_out;

    // Normalize: one warp per row.
    koleo_normalize<<<(NROWS * 32 + 255) / 256, 256>>>(in);

    // Gram argmax: 64 row-blocks x 4 j-splits, 64 KB dynamic smem.
    const int smem = (BK * BM + BK * BN) * (int)sizeof(float);  // 65536
    cudaFuncSetAttribute(koleo_argmax, cudaFuncAttributeMaxDynamicSharedMemorySize, smem);
    float* pv = nullptr; int* pi = nullptr;
    cudaGetSymbolAddress((void**)&pv, g_pv);
    cudaGetSymbolAddress((void**)&pi, g_pi);
    dim3 grid(NROWS / BM, JSPLIT);
    koleo_argmax<<<grid, 256, smem>>>(pv, pi);

    // Distances + log: one warp per row.
    koleo_dist<<<(NROWS * 32 + 255) / 256, 256>>>();

    // Final reduce.
    koleo_reduce<<<1, 256>>>(out);
}

// round 5
// speedup vs baseline: 8.1697x; 8.1697x over previous
#include <cuda_runtime.h>
#include <cuda_bf16.h>
#include <stdint.h>
#include <cstdint>
#include <math.h>

#define NROWS 8192
#define NDIM  384
#define EPSV  1e-8f

#define BM 128
#define BN 128
#define JSPLIT 2
#define TILES_PER_SPLIT (NROWS / (JSPLIT * BN))   // 32
#define DSB 784   // padded smem row stride in BYTES (384*2 + 16 pad)

// Scratch (static device memory; no allocations)
__device__ __align__(16) float g_x[(size_t)NROWS * NDIM];            // fp32 (distances)
__device__ __align__(16) __nv_bfloat16 g_xh[(size_t)NROWS * NDIM];   // bf16 (HMMA)
__device__ float g_pv[JSPLIT * NROWS];
__device__ int   g_pi[JSPLIT * NROWS];
__device__ float g_logd[NROWS];

__device__ __forceinline__ void ldsm_x4(unsigned& r0, unsigned& r1,
                                        unsigned& r2, unsigned& r3,
                                        unsigned addr) {
    asm volatile("ldmatrix.sync.aligned.m8n8.x4.shared.b16 {%0,%1,%2,%3}, [%4];"
                 : "=r"(r0), "=r"(r1), "=r"(r2), "=r"(r3) : "r"(addr));
}

__device__ __forceinline__ void mma16816(float* c, const unsigned* a,
                                         const unsigned* b) {
    asm volatile("mma.sync.aligned.m16n8k16.row.col.f32.bf16.bf16.f32 "
                 "{%0,%1,%2,%3}, {%4,%5,%6,%7}, {%8,%9}, {%0,%1,%2,%3};"
                 : "+f"(c[0]), "+f"(c[1]), "+f"(c[2]), "+f"(c[3])
                 : "r"(a[0]), "r"(a[1]), "r"(a[2]), "r"(a[3]),
                   "r"(b[0]), "r"(b[1]));
}

// ---------------------------------------------------------------------------
// Kernel 1: L2 normalize rows. One warp per row. Writes fp32 + bf16 copies.
// ---------------------------------------------------------------------------
__global__ void koleo_normalize(const float* __restrict__ in) {
    int gwarp = (blockIdx.x * blockDim.x + threadIdx.x) >> 5;
    int lane = threadIdx.x & 31;
    if (gwarp >= NROWS) return;

    const float4* a4 = (const float4*)(in + (size_t)gwarp * NDIM);
    float4 v[3];
    float ss = 0.0f;
#pragma unroll
    for (int t = 0; t < 3; t++) {
        v[t] = a4[lane + 32 * t];
        ss = fmaf(v[t].x, v[t].x, ss);
        ss = fmaf(v[t].y, v[t].y, ss);
        ss = fmaf(v[t].z, v[t].z, ss);
        ss = fmaf(v[t].w, v[t].w, ss);
    }
#pragma unroll
    for (int o = 16; o > 0; o >>= 1)
        ss += __shfl_xor_sync(0xffffffffu, ss, o);

    float inv = 1.0f / fmaxf(sqrtf(ss), EPSV);

    float4* o4 = (float4*)(g_x + (size_t)gwarp * NDIM);
    __nv_bfloat162* h2 = (__nv_bfloat162*)(g_xh + (size_t)gwarp * NDIM);
#pragma unroll
    for (int t = 0; t < 3; t++) {
        float4 w;
        w.x = v[t].x * inv; w.y = v[t].y * inv;
        w.z = v[t].z * inv; w.w = v[t].w * inv;
        o4[lane + 32 * t] = w;
        __nv_bfloat162 p0, p1;
        p0.x = __float2bfloat16_rn(w.x); p0.y = __float2bfloat16_rn(w.y);
        p1.x = __float2bfloat16_rn(w.z); p1.y = __float2bfloat16_rn(w.w);
        h2[(lane + 32 * t) * 2 + 0] = p0;
        h2[(lane + 32 * t) * 2 + 1] = p1;
    }
}

// ---------------------------------------------------------------------------
// Kernel 2: bf16 HMMA Gram tiles with fused running argmax.
// grid=(64, JSPLIT), 256 threads (8 warps: 2 in m x 4 in n; warp tile 64x32).
// A tile (128 rows x 384 k) resident in smem for the whole block.
// ---------------------------------------------------------------------------
__global__ void __launch_bounds__(256, 1) koleo_argmax(float* __restrict__ pv,
                                                       int* __restrict__ pi) {
    extern __shared__ __align__(16) unsigned char smraw[];
    unsigned char* as_raw = smraw;             // BM * DSB bytes
    unsigned char* bs_raw = smraw + BM * DSB;  // BM * DSB bytes

    const int tid = threadIdx.x;
    const int wid = tid >> 5;
    const int lane = tid & 31;
    const int wm = wid >> 2;   // 0..1
    const int wn = wid & 3;    // 0..3
    const int row0 = blockIdx.x * BM;
    const int sp = blockIdx.y;

    // ---- Load A tile (full K) once, resident ----
    {
        const uint4* src = (const uint4*)(g_xh + (size_t)row0 * NDIM);
#pragma unroll
        for (int i = 0; i < 24; i++) {
            int idx = tid + i * 256;
            int r = idx / 48, c = idx % 48;   // 48 uint4 per row (768 B)
            *(uint4*)(as_raw + r * DSB + c * 16) = src[r * 48 + c];
        }
    }

    unsigned as_base = (unsigned)__cvta_generic_to_shared(as_raw)
                       + (wm * 64 + (lane & 15)) * DSB + (lane >> 4) * 16;
    unsigned bs_base = (unsigned)__cvta_generic_to_shared(bs_raw)
                       + (wn * 32 + (lane & 15)) * DSB + (lane >> 4) * 16;

    float bestv[8];
    int   besti[8];
#pragma unroll
    for (int i = 0; i < 8; i++) { bestv[i] = -2.0f; besti[i] = 0x7fffffff; }

    const int r_in_warp = lane >> 2;      // 0..7
    const int c_in_quad = (lane & 3) * 2; // 0,2,4,6

    for (int jt = sp * TILES_PER_SPLIT; jt < (sp + 1) * TILES_PER_SPLIT; ++jt) {
        const int col0 = jt * BN;

        __syncthreads();   // prior iteration finished reading Bs
        {
            const uint4* src = (const uint4*)(g_xh + (size_t)col0 * NDIM);
#pragma unroll
            for (int i = 0; i < 24; i++) {
                int idx = tid + i * 256;
                int r = idx / 48, c = idx % 48;
                *(uint4*)(bs_raw + r * DSB + c * 16) = src[r * 48 + c];
            }
        }
        __syncthreads();

        float acc[4][4][4];
#pragma unroll
        for (int mi = 0; mi < 4; mi++)
#pragma unroll
            for (int ni = 0; ni < 4; ni++)
#pragma unroll
                for (int r = 0; r < 4; r++) acc[mi][ni][r] = 0.0f;

#pragma unroll 4
        for (int ks = 0; ks < NDIM / 16; ++ks) {   // 24 k-steps of 16
            const unsigned koff = ks * 32;         // bytes

            unsigned afr[4][4];
#pragma unroll
            for (int mi = 0; mi < 4; mi++)
                ldsm_x4(afr[mi][0], afr[mi][1], afr[mi][2], afr[mi][3],
                        as_base + mi * 16 * DSB + koff);

            unsigned bfr[4][2];
#pragma unroll
            for (int np = 0; np < 2; np++) {
                unsigned r0, r1, r2, r3;
                ldsm_x4(r0, r1, r2, r3, bs_base + np * 16 * DSB + koff);
                bfr[np * 2 + 0][0] = r0; bfr[np * 2 + 0][1] = r2;
                bfr[np * 2 + 1][0] = r1; bfr[np * 2 + 1][1] = r3;
            }

#pragma unroll
            for (int mi = 0; mi < 4; mi++)
#pragma unroll
                for (int ni = 0; ni < 4; ni++)
                    mma16816(acc[mi][ni], afr[mi], bfr[ni]);
        }

        // Fused epilogue: running argmax, skip diagonal.
#pragma unroll
        for (int mi = 0; mi < 4; mi++) {
#pragma unroll
            for (int h = 0; h < 2; h++) {
                const int bix = mi * 2 + h;
                const int gi = row0 + wm * 64 + mi * 16 + r_in_warp + 8 * h;
                float bv = bestv[bix];
                int bi = besti[bix];
#pragma unroll
                for (int ni = 0; ni < 4; ni++) {
#pragma unroll
                    for (int cc = 0; cc < 2; cc++) {
                        float v = acc[mi][ni][h * 2 + cc];
                        int gj = col0 + wn * 32 + ni * 8 + c_in_quad + cc;
                        if (gi != gj && (v > bv || (v == bv && gj < bi))) {
                            bv = v; bi = gj;
                        }
                    }
                }
                bestv[bix] = bv; besti[bix] = bi;
            }
        }
    }

    // Cross-thread reduction: each row seen by 16 threads (4 wn x 4 quad-cols).
    __syncthreads();
    float* rv = (float*)smraw;                    // 128*16 floats
    int* ri = (int*)(smraw + BM * 16 * 4);        // 128*16 ints
#pragma unroll
    for (int mi = 0; mi < 4; mi++) {
#pragma unroll
        for (int h = 0; h < 2; h++) {
            int lr = wm * 64 + mi * 16 + r_in_warp + 8 * h;
            int slot = wn * 4 + (lane & 3);
            rv[lr * 16 + slot] = bestv[mi * 2 + h];
            ri[lr * 16 + slot] = besti[mi * 2 + h];
        }
    }
    __syncthreads();
    if (tid < BM) {
        float bv = -2.0f; int bi = 0x7fffffff;
#pragma unroll
        for (int t = 0; t < 16; t++) {
            float v = rv[tid * 16 + t];
            int ix = ri[tid * 16 + t];
            if (v > bv || (v == bv && ix < bi)) { bv = v; bi = ix; }
        }
        pv[sp * NROWS + row0 + tid] = bv;
        pi[sp * NROWS + row0 + tid] = bi;
    }
}

// ---------------------------------------------------------------------------
// Kernel 3: merge split partials, compute log pairwise distance. Warp/row.
// ---------------------------------------------------------------------------
__global__ void koleo_dist() {
    int gwarp = (blockIdx.x * blockDim.x + threadIdx.x) >> 5;
    int lane = threadIdx.x & 31;
    if (gwarp >= NROWS) return;

    int bi = 0;
    if (lane == 0) {
        float bv = -2.0f; bi = 0x7fffffff;
        for (int s = 0; s < JSPLIT; s++) {
            float v = g_pv[s * NROWS + gwarp];
            int ix = g_pi[s * NROWS + gwarp];
            if (v > bv || (v == bv && ix < bi)) { bv = v; bi = ix; }
        }
    }
    bi = __shfl_sync(0xffffffffu, bi, 0);

    const float4* a4 = (const float4*)(g_x + (size_t)gwarp * NDIM);
    const float4* b4 = (const float4*)(g_x + (size_t)bi * NDIM);
    float ss = 0.0f;
#pragma unroll
    for (int t = 0; t < 3; t++) {
        float4 a = a4[lane + 32 * t];
        float4 b = b4[lane + 32 * t];
        float dx = a.x - b.x + EPSV;
        float dy = a.y - b.y + EPSV;
        float dz = a.z - b.z + EPSV;
        float dw = a.w - b.w + EPSV;
        ss = fmaf(dx, dx, ss);
        ss = fmaf(dy, dy, ss);
        ss = fmaf(dz, dz, ss);
        ss = fmaf(dw, dw, ss);
    }
#pragma unroll
    for (int o = 16; o > 0; o >>= 1)
        ss += __shfl_xor_sync(0xffffffffu, ss, o);

    if (lane == 0)
        g_logd[gwarp] = logf(sqrtf(ss) + EPSV);
}

// ---------------------------------------------------------------------------
// Kernel 4: deterministic reduction -> loss scalar.
// ---------------------------------------------------------------------------
__global__ void koleo_reduce(float* __restrict__ out) {
    __shared__ float s[256];
    float acc = 0.0f;
    for (int i = threadIdx.x; i < NROWS; i += 256) acc += g_logd[i];
    s[threadIdx.x] = acc;
    __syncthreads();
    for (int w = 128; w > 0; w >>= 1) {
        if (threadIdx.x < w) s[threadIdx.x] += s[threadIdx.x + w];
        __syncthreads();
    }
    if (threadIdx.x == 0) out[0] = -s[0] / (float)NROWS;
}

// ---------------------------------------------------------------------------
extern "C" void kernel_launch(void* const* d_in, const int* in_sizes, int n_in,
                              void* d_out, int out_size) {
    const float* in = (const float*)d_in[0];
    float* out = (float*)d_out;

    koleo_normalize<<<(NROWS * 32 + 255) / 256, 256>>>(in);

    const int smem = 2 * BM * DSB;  // 200704 bytes
    cudaFuncSetAttribute(koleo_argmax, cudaFuncAttributeMaxDynamicSharedMemorySize, smem);
    float* pv = nullptr; int* pi = nullptr;
    cudaGetSymbolAddress((void**)&pv, g_pv);
    cudaGetSymbolAddress((void**)&pi, g_pi);
    dim3 grid(NROWS / BM, JSPLIT);
    koleo_argmax<<<grid, 256, smem>>>(pv, pi);

    koleo_dist<<<(NROWS * 32 + 255) / 256, 256>>>();
    koleo_reduce<<<1, 256>>>(out);
}

// round 8
// speedup vs baseline: 11.8958x; 1.4561x over previous
#include <cuda_runtime.h>
#include <cuda_bf16.h>
#include <stdint.h>
#include <math.h>

#define NROWS 8192
#define NDIM  384
#define EPSV  1e-8f

#define BM 128
#define BN 128
#define NB (NROWS / BM)            // 64 row/col blocks
#define NTILES (NB * (NB + 1) / 2) // 2080 upper-triangle tiles
#define KC 128                     // k-elements per chunk
#define NCHUNK (NDIM / KC)         // 3
#define SB2 272                    // smem row stride bytes (256 + 16 pad)
#define ABUF (BM * SB2)            // 34816 B per matrix chunk
#define SMEM_TOTAL (4 * ABUF)      // 139264: [A0][B0][A1][B1]

// Scratch (static device memory; no allocations)
__device__ __align__(16) float g_x[(size_t)NROWS * NDIM];            // fp32 (distances)
__device__ __align__(16) __nv_bfloat16 g_xh[(size_t)NROWS * NDIM];   // bf16 (HMMA)
__device__ unsigned long long g_best[NROWS];                          // packed (val,idx)
__device__ float g_logd[NROWS];

__device__ __forceinline__ void ldsm_x4(unsigned& r0, unsigned& r1,
                                        unsigned& r2, unsigned& r3,
                                        unsigned addr) {
    asm volatile("ldmatrix.sync.aligned.m8n8.x4.shared.b16 {%0,%1,%2,%3}, [%4];"
                 : "=r"(r0), "=r"(r1), "=r"(r2), "=r"(r3) : "r"(addr));
}
__device__ __forceinline__ void mma16816(float* c, const unsigned* a,
                                         const unsigned* b) {
    asm volatile("mma.sync.aligned.m16n8k16.row.col.f32.bf16.bf16.f32 "
                 "{%0,%1,%2,%3}, {%4,%5,%6,%7}, {%8,%9}, {%0,%1,%2,%3};"
                 : "+f"(c[0]), "+f"(c[1]), "+f"(c[2]), "+f"(c[3])
                 : "r"(a[0]), "r"(a[1]), "r"(a[2]), "r"(a[3]),
                   "r"(b[0]), "r"(b[1]));
}
__device__ __forceinline__ void cp_async16(unsigned dst, const void* src) {
    asm volatile("cp.async.cg.shared.global [%0], [%1], 16;"
                 :: "r"(dst), "l"(src) : "memory");
}
__device__ __forceinline__ unsigned long long pack_best(float v, int idx) {
    unsigned u = __float_as_uint(v);
    u = (u & 0x80000000u) ? ~u : (u | 0x80000000u);
    return ((unsigned long long)u << 32) | (unsigned)(0xFFFFFFFFu - (unsigned)idx);
}

// ---------------------------------------------------------------------------
// Kernel 1: L2 normalize rows (warp/row); also zero g_best for this run.
// ---------------------------------------------------------------------------
__global__ void koleo_normalize(const float* __restrict__ in) {
    int gwarp = (blockIdx.x * blockDim.x + threadIdx.x) >> 5;
    int lane = threadIdx.x & 31;
    if (gwarp >= NROWS) return;

    const float4* a4 = (const float4*)(in + (size_t)gwarp * NDIM);
    float4 v[3];
    float ss = 0.0f;
#pragma unroll
    for (int t = 0; t < 3; t++) {
        v[t] = a4[lane + 32 * t];
        ss = fmaf(v[t].x, v[t].x, ss);
        ss = fmaf(v[t].y, v[t].y, ss);
        ss = fmaf(v[t].z, v[t].z, ss);
        ss = fmaf(v[t].w, v[t].w, ss);
    }
#pragma unroll
    for (int o = 16; o > 0; o >>= 1)
        ss += __shfl_xor_sync(0xffffffffu, ss, o);

    float inv = 1.0f / fmaxf(sqrtf(ss), EPSV);

    if (lane == 0) g_best[gwarp] = 0ull;   // reset accumulator every launch

    float4* o4 = (float4*)(g_x + (size_t)gwarp * NDIM);
    __nv_bfloat162* h2 = (__nv_bfloat162*)(g_xh + (size_t)gwarp * NDIM);
#pragma unroll
    for (int t = 0; t < 3; t++) {
        float4 w;
        w.x = v[t].x * inv; w.y = v[t].y * inv;
        w.z = v[t].z * inv; w.w = v[t].w * inv;
        o4[lane + 32 * t] = w;
        __nv_bfloat162 p0, p1;
        p0.x = __float2bfloat16_rn(w.x); p0.y = __float2bfloat16_rn(w.y);
        p1.x = __float2bfloat16_rn(w.z); p1.y = __float2bfloat16_rn(w.w);
        h2[(lane + 32 * t) * 2 + 0] = p0;
        h2[(lane + 32 * t) * 2 + 1] = p1;
    }
}

// ---------------------------------------------------------------------------
// Kernel 2: upper-triangle Gram tiles. One 128x128 tile per CTA (2080 CTAs).
// Off-diagonal tiles update rows (bi block) AND columns (bj block, transpose).
// cp.async double-buffered k-pipeline (3 chunks of 128).
// ---------------------------------------------------------------------------
__global__ void __launch_bounds__(256) koleo_argmax(unsigned long long* __restrict__ best) {
    extern __shared__ __align__(16) unsigned char smraw[];
    const unsigned smb = (unsigned)__cvta_generic_to_shared(smraw);

    // decode upper-triangle tile (bi <= bj)
    int bi = 0, rem = blockIdx.x;
    while (rem >= NB - bi) { rem -= NB - bi; bi++; }
    const int bj = bi + rem;
    const int rowA0 = bi * BM;
    const int rowB0 = bj * BN;
    const bool diag = (bi == bj);

    const int tid = threadIdx.x;
    const int wid = tid >> 5;
    const int lane = tid & 31;
    const int wm = wid >> 2;   // 0..1
    const int wn = wid & 3;    // 0..3
    const int r_in_warp = lane >> 2;      // 0..7
    const int c_in_quad = (lane & 3) * 2; // 0,2,4,6

    // chunk issue helper (inlined manually): 8 cp.async16 per thread per matrix
    const int r_ld = tid >> 1;            // unused pattern; use q-based below

    float acc[4][4][4];
#pragma unroll
    for (int mi = 0; mi < 4; mi++)
#pragma unroll
        for (int ni = 0; ni < 4; ni++)
#pragma unroll
            for (int r = 0; r < 4; r++) acc[mi][ni][r] = 0.0f;

    // ---- issue chunk 0 ----
    {
        const unsigned ab = smb;              // buf 0: A
        const unsigned bb = smb + ABUF;       // buf 0: B
#pragma unroll
        for (int i = 0; i < 8; i++) {
            int q = i * 256 + tid;
            int r = q >> 4, s = q & 15;
            cp_async16(ab + r * SB2 + s * 16,
                       (const void*)(g_xh + (size_t)(rowA0 + r) * NDIM + s * 8));
        }
#pragma unroll
        for (int i = 0; i < 8; i++) {
            int q = i * 256 + tid;
            int r = q >> 4, s = q & 15;
            cp_async16(bb + r * SB2 + s * 16,
                       (const void*)(g_xh + (size_t)(rowB0 + r) * NDIM + s * 8));
        }
        asm volatile("cp.async.commit_group;" ::: "memory");
    }

    const unsigned as_off = (wm * 64 + (lane & 15)) * SB2 + (lane >> 4) * 16;
    const unsigned bs_off = (wn * 32 + (lane & 15)) * SB2 + (lane >> 4) * 16;

#pragma unroll
    for (int c = 0; c < NCHUNK; c++) {
        if (c + 1 < NCHUNK) {
            const unsigned ab = smb + ((c + 1) & 1) * 2 * ABUF;
            const unsigned bb = ab + ABUF;
            const size_t kof = (size_t)(c + 1) * KC;
#pragma unroll
            for (int i = 0; i < 8; i++) {
                int q = i * 256 + tid;
                int r = q >> 4, s = q & 15;
                cp_async16(ab + r * SB2 + s * 16,
                           (const void*)(g_xh + (size_t)(rowA0 + r) * NDIM + kof + s * 8));
            }
#pragma unroll
            for (int i = 0; i < 8; i++) {
                int q = i * 256 + tid;
                int r = q >> 4, s = q & 15;
                cp_async16(bb + r * SB2 + s * 16,
                           (const void*)(g_xh + (size_t)(rowB0 + r) * NDIM + kof + s * 8));
            }
            asm volatile("cp.async.commit_group;" ::: "memory");
            asm volatile("cp.async.wait_group 1;" ::: "memory");
        } else {
            asm volatile("cp.async.wait_group 0;" ::: "memory");
        }
        __syncthreads();

        const unsigned as_base = smb + (c & 1) * 2 * ABUF + as_off;
        const unsigned bs_base = smb + (c & 1) * 2 * ABUF + ABUF + bs_off;

#pragma unroll
        for (int ks = 0; ks < KC / 16; ++ks) {   // 8 k-steps of 16
            const unsigned koff = ks * 32;

            unsigned afr[4][4];
#pragma unroll
            for (int mi = 0; mi < 4; mi++)
                ldsm_x4(afr[mi][0], afr[mi][1], afr[mi][2], afr[mi][3],
                        as_base + mi * 16 * SB2 + koff);

            unsigned bfr[4][2];
#pragma unroll
            for (int np = 0; np < 2; np++) {
                unsigned r0, r1, r2, r3;
                ldsm_x4(r0, r1, r2, r3, bs_base + np * 16 * SB2 + koff);
                bfr[np * 2 + 0][0] = r0; bfr[np * 2 + 0][1] = r2;
                bfr[np * 2 + 1][0] = r1; bfr[np * 2 + 1][1] = r3;
            }

#pragma unroll
            for (int mi = 0; mi < 4; mi++)
#pragma unroll
                for (int ni = 0; ni < 4; ni++)
                    mma16816(acc[mi][ni], afr[mi], bfr[ni]);
        }
        __syncthreads();
    }

    // ===== Epilogue =====
    // Reduction buffers overlap the (now idle) chunk buffers.
    float* rv = (float*)smraw;                       // 128*16
    int*   ri = (int*)(smraw + 8192);                // 128*16
    float* cv = (float*)(smraw + 16384);             // 128*16
    int*   ci = (int*)(smraw + 24576);               // 128*16

    // Row-direction candidates (per thread: 8 row slots over its 8 columns).
#pragma unroll
    for (int mi = 0; mi < 4; mi++) {
#pragma unroll
        for (int h = 0; h < 2; h++) {
            const int lr = wm * 64 + mi * 16 + r_in_warp + 8 * h;
            const int gi = rowA0 + lr;
            float bv = -2.0f; int bx = 0x7fffffff;
#pragma unroll
            for (int ni = 0; ni < 4; ni++) {
#pragma unroll
                for (int cc = 0; cc < 2; cc++) {
                    float v = acc[mi][ni][h * 2 + cc];
                    int gj = rowB0 + wn * 32 + ni * 8 + c_in_quad + cc;
                    if (gi != gj && (v > bv || (v == bv && gj < bx))) { bv = v; bx = gj; }
                }
            }
            rv[lr * 16 + wn * 4 + (lane & 3)] = bv;
            ri[lr * 16 + wn * 4 + (lane & 3)] = bx;
        }
    }
    // Column-direction candidates (transpose reuse), off-diagonal tiles only.
    if (!diag) {
#pragma unroll
        for (int ni = 0; ni < 4; ni++) {
#pragma unroll
            for (int cc = 0; cc < 2; cc++) {
                const int lc = wn * 32 + ni * 8 + c_in_quad + cc;
                float bv = -2.0f; int bx = 0x7fffffff;
#pragma unroll
                for (int mi = 0; mi < 4; mi++) {
#pragma unroll
                    for (int h = 0; h < 2; h++) {
                        float v = acc[mi][ni][h * 2 + cc];
                        int gi = rowA0 + wm * 64 + mi * 16 + r_in_warp + 8 * h;
                        if (v > bv || (v == bv && gi < bx)) { bv = v; bx = gi; }
                    }
                }
                cv[lc * 16 + wm * 8 + r_in_warp] = bv;
                ci[lc * 16 + wm * 8 + r_in_warp] = bx;
            }
        }
    }
    __syncthreads();

    if (tid < BM) {
        float bv = -2.0f; int bx = 0x7fffffff;
#pragma unroll
        for (int t = 0; t < 16; t++) {
            float v = rv[tid * 16 + t];
            int ix = ri[tid * 16 + t];
            if (v > bv || (v == bv && ix < bx)) { bv = v; bx = ix; }
        }
        atomicMax(&best[rowA0 + tid], pack_best(bv, bx));
    } else if (!diag) {
        const int col = tid - BM;
        float bv = -2.0f; int bx = 0x7fffffff;
#pragma unroll
        for (int t = 0; t < 16; t++) {
            float v = cv[col * 16 + t];
            int ix = ci[col * 16 + t];
            if (v > bv || (v == bv && ix < bx)) { bv = v; bx = ix; }
        }
        atomicMax(&best[rowB0 + col], pack_best(bv, bx));
    }
}

// ---------------------------------------------------------------------------
// Kernel 3: decode neighbor, compute log pairwise distance. Warp/row.
// ---------------------------------------------------------------------------
__global__ void koleo_dist() {
    int gwarp = (blockIdx.x * blockDim.x + threadIdx.x) >> 5;
    int lane = threadIdx.x & 31;
    if (gwarp >= NROWS) return;

    unsigned long long key = g_best[gwarp];
    int bi = (int)(0xFFFFFFFFu - (unsigned)(key & 0xFFFFFFFFull));

    const float4* a4 = (const float4*)(g_x + (size_t)gwarp * NDIM);
    const float4* b4 = (const float4*)(g_x + (size_t)bi * NDIM);
    float ss = 0.0f;
#pragma unroll
    for (int t = 0; t < 3; t++) {
        float4 a = a4[lane + 32 * t];
        float4 b = b4[lane + 32 * t];
        float dx = a.x - b.x + EPSV;
        float dy = a.y - b.y + EPSV;
        float dz = a.z - b.z + EPSV;
        float dw = a.w - b.w + EPSV;
        ss = fmaf(dx, dx, ss);
        ss = fmaf(dy, dy, ss);
        ss = fmaf(dz, dz, ss);
        ss = fmaf(dw, dw, ss);
    }
#pragma unroll
    for (int o = 16; o > 0; o >>= 1)
        ss += __shfl_xor_sync(0xffffffffu, ss, o);

    if (lane == 0)
        g_logd[gwarp] = logf(sqrtf(ss) + EPSV);
}

// ---------------------------------------------------------------------------
// Kernel 4: deterministic reduction -> loss scalar.
// ---------------------------------------------------------------------------
__global__ void koleo_reduce(float* __restrict__ out) {
    __shared__ float s[256];
    float acc = 0.0f;
    for (int i = threadIdx.x; i < NROWS; i += 256) acc += g_logd[i];
    s[threadIdx.x] = acc;
    __syncthreads();
    for (int w = 128; w > 0; w >>= 1) {
        if (threadIdx.x < w) s[threadIdx.x] += s[threadIdx.x + w];
        __syncthreads();
    }
    if (threadIdx.x == 0) out[0] = -s[0] / (float)NROWS;
}

// ---------------------------------------------------------------------------
extern "C" void kernel_launch(void* const* d_in, const int* in_sizes, int n_in,
                              void* d_out, int out_size) {
    const float* in = (const float*)d_in[0];
    float* out = (float*)d_out;

    koleo_normalize<<<(NROWS * 32 + 255) / 256, 256>>>(in);

    cudaFuncSetAttribute(koleo_argmax, cudaFuncAttributeMaxDynamicSharedMemorySize,
                         SMEM_TOTAL);
    unsigned long long* best = nullptr;
    cudaGetSymbolAddress((void**)&best, g_best);
    koleo_argmax<<<NTILES, 256, SMEM_TOTAL>>>(best);

    koleo_dist<<<(NROWS * 32 + 255) / 256, 256>>>();
    koleo_reduce<<<1, 256>>>(out);
}

// round 9
// speedup vs baseline: 12.7708x; 1.0736x over previous
#include <cuda_runtime.h>
#include <cuda_bf16.h>
#include <stdint.h>
#include <math.h>

#define NROWS 8192
#define NDIM  384
#define EPSV  1e-8f

#define BM 128
#define BN 128
#define NB (NROWS / BM)            // 64
#define NTILES (NB * (NB + 1) / 2) // 2080
#define NSEG 148                   // persistent CTAs (one per SM)
#define KC 128                     // k per B chunk
#define NCHUNK (NDIM / KC)         // 3

#define ASB 784                    // A smem row stride bytes (768 + 16)
#define ABYTES (BM * ASB)          // 100352
#define BSB 272                    // B smem row stride bytes (256 + 16)
#define BBUF (BM * BSB)            // 34816
#define RED_OFF (ABYTES + 2 * BBUF)        // 169984
#define SMEM_TOTAL (RED_OFF + 32768)       // 202752

// Scratch (static device memory; no allocations)
__device__ __align__(16) float g_x[(size_t)NROWS * NDIM];            // fp32 (distances)
__device__ __align__(16) __nv_bfloat16 g_xh[(size_t)NROWS * NDIM];   // bf16 (HMMA)
__device__ unsigned long long g_best[NROWS];                          // packed (val,idx)
__device__ float g_logd[NROWS];

__device__ __forceinline__ void ldsm_x4(unsigned& r0, unsigned& r1,
                                        unsigned& r2, unsigned& r3,
                                        unsigned addr) {
    asm volatile("ldmatrix.sync.aligned.m8n8.x4.shared.b16 {%0,%1,%2,%3}, [%4];"
                 : "=r"(r0), "=r"(r1), "=r"(r2), "=r"(r3) : "r"(addr));
}
__device__ __forceinline__ void mma16816(float* c, const unsigned* a,
                                         const unsigned* b) {
    asm volatile("mma.sync.aligned.m16n8k16.row.col.f32.bf16.bf16.f32 "
                 "{%0,%1,%2,%3}, {%4,%5,%6,%7}, {%8,%9}, {%0,%1,%2,%3};"
                 : "+f"(c[0]), "+f"(c[1]), "+f"(c[2]), "+f"(c[3])
                 : "r"(a[0]), "r"(a[1]), "r"(a[2]), "r"(a[3]),
                   "r"(b[0]), "r"(b[1]));
}
__device__ __forceinline__ void cp_async16(unsigned dst, const void* src) {
    asm volatile("cp.async.cg.shared.global [%0], [%1], 16;"
                 :: "r"(dst), "l"(src) : "memory");
}
__device__ __forceinline__ void cp_commit() {
    asm volatile("cp.async.commit_group;" ::: "memory");
}
__device__ __forceinline__ void cp_wait1() {
    asm volatile("cp.async.wait_group 1;" ::: "memory");
}
__device__ __forceinline__ void cp_wait0() {
    asm volatile("cp.async.wait_group 0;" ::: "memory");
}
__device__ __forceinline__ unsigned long long pack_best(float v, int idx) {
    unsigned u = __float_as_uint(v);
    u = (u & 0x80000000u) ? ~u : (u | 0x80000000u);
    return ((unsigned long long)u << 32) | (unsigned)(0xFFFFFFFFu - (unsigned)idx);
}
__device__ __forceinline__ void decode_tile(int t, int& bi, int& bj) {
    int b = 0, rem = t;
    while (rem >= NB - b) { rem -= NB - b; b++; }
    bi = b; bj = b + rem;
}

// ---------------------------------------------------------------------------
// Kernel 1: L2 normalize rows (warp/row); also zero g_best for this run.
// ---------------------------------------------------------------------------
__global__ void koleo_normalize(const float* __restrict__ in) {
    int gwarp = (blockIdx.x * blockDim.x + threadIdx.x) >> 5;
    int lane = threadIdx.x & 31;
    if (gwarp >= NROWS) return;

    const float4* a4 = (const float4*)(in + (size_t)gwarp * NDIM);
    float4 v[3];
    float ss = 0.0f;
#pragma unroll
    for (int t = 0; t < 3; t++) {
        v[t] = a4[lane + 32 * t];
        ss = fmaf(v[t].x, v[t].x, ss);
        ss = fmaf(v[t].y, v[t].y, ss);
        ss = fmaf(v[t].z, v[t].z, ss);
        ss = fmaf(v[t].w, v[t].w, ss);
    }
#pragma unroll
    for (int o = 16; o > 0; o >>= 1)
        ss += __shfl_xor_sync(0xffffffffu, ss, o);

    float inv = 1.0f / fmaxf(sqrtf(ss), EPSV);

    if (lane == 0) g_best[gwarp] = 0ull;

    float4* o4 = (float4*)(g_x + (size_t)gwarp * NDIM);
    __nv_bfloat162* h2 = (__nv_bfloat162*)(g_xh + (size_t)gwarp * NDIM);
#pragma unroll
    for (int t = 0; t < 3; t++) {
        float4 w;
        w.x = v[t].x * inv; w.y = v[t].y * inv;
        w.z = v[t].z * inv; w.w = v[t].w * inv;
        o4[lane + 32 * t] = w;
        __nv_bfloat162 p0, p1;
        p0.x = __float2bfloat16_rn(w.x); p0.y = __float2bfloat16_rn(w.y);
        p1.x = __float2bfloat16_rn(w.z); p1.y = __float2bfloat16_rn(w.w);
        h2[(lane + 32 * t) * 2 + 0] = p0;
        h2[(lane + 32 * t) * 2 + 1] = p1;
    }
}

// ---------------------------------------------------------------------------
// Kernel 2: persistent upper-triangle Gram tiles (148 CTAs, ~14 tiles each).
// A block resident in smem across a bi-run; B double-buffered with cross-tile
// chunk-0 prefetch; row-argmax accumulated in registers across the run.
// ---------------------------------------------------------------------------
__global__ void __launch_bounds__(256, 1) koleo_argmax(unsigned long long* __restrict__ best) {
    extern __shared__ __align__(16) unsigned char smraw[];
    const unsigned smb = (unsigned)__cvta_generic_to_shared(smraw);
    const unsigned smA = smb;
    const unsigned smB = smb + ABYTES;

    const int tid = threadIdx.x;
    const int wid = tid >> 5;
    const int lane = tid & 31;
    const int wm = wid >> 2;
    const int wn = wid & 3;
    const int r_in_warp = lane >> 2;
    const int c_in_quad = (lane & 3) * 2;

    const int t_begin = (int)(((long long)blockIdx.x * NTILES) / NSEG);
    const int t_end   = (int)(((long long)(blockIdx.x + 1) * NTILES) / NSEG);

    // reduction buffers
    float* rv = (float*)(smraw + RED_OFF);
    int*   ri = (int*)(smraw + RED_OFF + 8192);
    float* cv = (float*)(smraw + RED_OFF + 16384);
    int*   ci = (int*)(smraw + RED_OFF + 24576);

    const unsigned as_off = (wm * 64 + (lane & 15)) * ASB + (lane >> 4) * 16;
    const unsigned bs_off = (wn * 32 + (lane & 15)) * BSB + (lane >> 4) * 16;

    // issue helpers (inlined via lambdas)
    auto issue_A = [&](int bi) {
#pragma unroll
        for (int i = 0; i < 24; i++) {
            int q = i * 256 + tid;
            int r = q / 48, c = q % 48;
            cp_async16(smA + r * ASB + c * 16,
                       (const void*)(g_xh + (size_t)(bi * BM + r) * NDIM + c * 8));
        }
    };
    auto issue_B = [&](int bj, int chunk, int buf) {
        const unsigned bb = smB + buf * BBUF;
        const size_t kof = (size_t)chunk * KC;
#pragma unroll
        for (int i = 0; i < 8; i++) {
            int q = i * 256 + tid;
            int r = q >> 4, s = q & 15;
            cp_async16(bb + r * BSB + s * 16,
                       (const void*)(g_xh + (size_t)(bj * BM + r) * NDIM + kof + s * 8));
        }
    };

    float rbv[8];
    int   rbx[8];
#pragma unroll
    for (int i = 0; i < 8; i++) { rbv[i] = -2.0f; rbx[i] = 0x7fffffff; }

    // prime the pipeline
    int bi, bj;
    decode_tile(t_begin, bi, bj);
    int a_bi = bi;
    issue_A(bi);
    issue_B(bj, 0, 0);
    cp_commit();
    int par = 0;   // buffer holding next chunk to consume

    for (int t = t_begin; t < t_end; ++t) {
        const bool has_next = (t + 1 < t_end);
        int nbi = -1, nbj = -1;
        if (has_next) decode_tile(t + 1, nbi, nbj);
        const bool diag = (bi == bj);

        float acc[4][4][4];
#pragma unroll
        for (int mi = 0; mi < 4; mi++)
#pragma unroll
            for (int ni = 0; ni < 4; ni++)
#pragma unroll
                for (int r = 0; r < 4; r++) acc[mi][ni][r] = 0.0f;

#pragma unroll
        for (int c = 0; c < NCHUNK; c++) {
            bool issued = false;
            if (c < NCHUNK - 1) {
                issue_B(bj, c + 1, par ^ 1); cp_commit(); issued = true;
            } else if (has_next && nbi == a_bi) {
                issue_B(nbj, 0, par ^ 1); cp_commit(); issued = true;  // prefetch
            }
            if (issued) cp_wait1(); else cp_wait0();
            __syncthreads();

            const unsigned as_base = smA + as_off;
            const unsigned bs_base = smB + par * BBUF + bs_off;
#pragma unroll
            for (int ksc = 0; ksc < KC / 16; ++ksc) {
                const unsigned akoff = (c * 8 + ksc) * 32;
                const unsigned bkoff = ksc * 32;

                unsigned afr[4][4];
#pragma unroll
                for (int mi = 0; mi < 4; mi++)
                    ldsm_x4(afr[mi][0], afr[mi][1], afr[mi][2], afr[mi][3],
                            as_base + mi * 16 * ASB + akoff);

                unsigned bfr[4][2];
#pragma unroll
                for (int np = 0; np < 2; np++) {
                    unsigned r0, r1, r2, r3;
                    ldsm_x4(r0, r1, r2, r3, bs_base + np * 16 * BSB + bkoff);
                    bfr[np * 2 + 0][0] = r0; bfr[np * 2 + 0][1] = r2;
                    bfr[np * 2 + 1][0] = r1; bfr[np * 2 + 1][1] = r3;
                }

#pragma unroll
                for (int mi = 0; mi < 4; mi++)
#pragma unroll
                    for (int ni = 0; ni < 4; ni++)
                        mma16816(acc[mi][ni], afr[mi], bfr[ni]);
            }
            __syncthreads();
            par ^= 1;
        }

        // ===== Epilogue =====
        const bool flush = !has_next || (nbi != bi);

        // Row direction: accumulate in registers (run-long).
#pragma unroll
        for (int mi = 0; mi < 4; mi++) {
#pragma unroll
            for (int h = 0; h < 2; h++) {
                const int six = mi * 2 + h;
                const int gi = bi * BM + wm * 64 + mi * 16 + r_in_warp + 8 * h;
                float bv = rbv[six]; int bx = rbx[six];
#pragma unroll
                for (int ni = 0; ni < 4; ni++) {
#pragma unroll
                    for (int cc = 0; cc < 2; cc++) {
                        float v = acc[mi][ni][h * 2 + cc];
                        int gj = bj * BN + wn * 32 + ni * 8 + c_in_quad + cc;
                        if (gi != gj && (v > bv || (v == bv && gj < bx))) {
                            bv = v; bx = gj;
                        }
                    }
                }
                rbv[six] = bv; rbx[six] = bx;
            }
        }

        // Column candidates to smem (off-diagonal tiles only).
        if (!diag) {
#pragma unroll
            for (int ni = 0; ni < 4; ni++) {
#pragma unroll
                for (int cc = 0; cc < 2; cc++) {
                    const int lc = wn * 32 + ni * 8 + c_in_quad + cc;
                    float bv = -2.0f; int bx = 0x7fffffff;
#pragma unroll
                    for (int mi = 0; mi < 4; mi++) {
#pragma unroll
                        for (int h = 0; h < 2; h++) {
                            float v = acc[mi][ni][h * 2 + cc];
                            int gi = bi * BM + wm * 64 + mi * 16 + r_in_warp + 8 * h;
                            if (v > bv || (v == bv && gi < bx)) { bv = v; bx = gi; }
                        }
                    }
                    cv[lc * 16 + wm * 8 + r_in_warp] = bv;
                    ci[lc * 16 + wm * 8 + r_in_warp] = bx;
                }
            }
        }
        // Row flush: dump run-long register bests to smem.
        if (flush) {
#pragma unroll
            for (int mi = 0; mi < 4; mi++) {
#pragma unroll
                for (int h = 0; h < 2; h++) {
                    const int lr = wm * 64 + mi * 16 + r_in_warp + 8 * h;
                    rv[lr * 16 + wn * 4 + (lane & 3)] = rbv[mi * 2 + h];
                    ri[lr * 16 + wn * 4 + (lane & 3)] = rbx[mi * 2 + h];
                }
            }
        }

        if (!diag || flush) {
            __syncthreads();
            if (!diag && tid < BM) {
                float bv = -2.0f; int bx = 0x7fffffff;
#pragma unroll
                for (int s = 0; s < 16; s++) {
                    float v = cv[tid * 16 + s];
                    int ix = ci[tid * 16 + s];
                    if (v > bv || (v == bv && ix < bx)) { bv = v; bx = ix; }
                }
                atomicMax(&best[bj * BN + tid], pack_best(bv, bx));
            }
            if (flush && tid >= BM) {
                const int row = tid - BM;
                float bv = -2.0f; int bx = 0x7fffffff;
#pragma unroll
                for (int s = 0; s < 16; s++) {
                    float v = rv[row * 16 + s];
                    int ix = ri[row * 16 + s];
                    if (v > bv || (v == bv && ix < bx)) { bv = v; bx = ix; }
                }
                atomicMax(&best[bi * BM + row], pack_best(bv, bx));
            }
        }
        if (flush) {
#pragma unroll
            for (int i = 0; i < 8; i++) { rbv[i] = -2.0f; rbx[i] = 0x7fffffff; }
        }

        // Advance: boundary loads for the next tile.
        if (has_next) {
            if (nbi != a_bi) {
                __syncthreads();   // reduce readers done before A overwrite
                issue_A(nbi);
                a_bi = nbi;
                issue_B(nbj, 0, par);   // prefetch was skipped
                cp_commit();
            }
            bi = nbi; bj = nbj;
        }
    }
}

// ---------------------------------------------------------------------------
// Kernel 3: decode neighbor, compute log pairwise distance. Warp/row.
// ---------------------------------------------------------------------------
__global__ void koleo_dist() {
    int gwarp = (blockIdx.x * blockDim.x + threadIdx.x) >> 5;
    int lane = threadIdx.x & 31;
    if (gwarp >= NROWS) return;

    unsigned long long key = g_best[gwarp];
    int bi = (int)(0xFFFFFFFFu - (unsigned)(key & 0xFFFFFFFFull));

    const float4* a4 = (const float4*)(g_x + (size_t)gwarp * NDIM);
    const float4* b4 = (const float4*)(g_x + (size_t)bi * NDIM);
    float ss = 0.0f;
#pragma unroll
    for (int t = 0; t < 3; t++) {
        float4 a = a4[lane + 32 * t];
        float4 b = b4[lane + 32 * t];
        float dx = a.x - b.x + EPSV;
        float dy = a.y - b.y + EPSV;
        float dz = a.z - b.z + EPSV;
        float dw = a.w - b.w + EPSV;
        ss = fmaf(dx, dx, ss);
        ss = fmaf(dy, dy, ss);
        ss = fmaf(dz, dz, ss);
        ss = fmaf(dw, dw, ss);
    }
#pragma unroll
    for (int o = 16; o > 0; o >>= 1)
        ss += __shfl_xor_sync(0xffffffffu, ss, o);

    if (lane == 0)
        g_logd[gwarp] = logf(sqrtf(ss) + EPSV);
}

// ---------------------------------------------------------------------------
// Kernel 4: deterministic reduction -> loss scalar.
// ---------------------------------------------------------------------------
__global__ void koleo_reduce(float* __restrict__ out) {
    __shared__ float s[256];
    float acc = 0.0f;
    for (int i = threadIdx.x; i < NROWS; i += 256) acc += g_logd[i];
    s[threadIdx.x] = acc;
    __syncthreads();
    for (int w = 128; w > 0; w >>= 1) {
        if (threadIdx.x < w) s[threadIdx.x] += s[threadIdx.x + w];
        __syncthreads();
    }
    if (threadIdx.x == 0) out[0] = -s[0] / (float)NROWS;
}

// ---------------------------------------------------------------------------
extern "C" void kernel_launch(void* const* d_in, const int* in_sizes, int n_in,
                              void* d_out, int out_size) {
    const float* in = (const float*)d_in[0];
    float* out = (float*)d_out;

    koleo_normalize<<<(NROWS * 32 + 255) / 256, 256>>>(in);

    cudaFuncSetAttribute(koleo_argmax, cudaFuncAttributeMaxDynamicSharedMemorySize,
                         SMEM_TOTAL);
    unsigned long long* best = nullptr;
    cudaGetSymbolAddress((void**)&best, g_best);
    koleo_argmax<<<NSEG, 256, SMEM_TOTAL>>>(best);

    koleo_dist<<<(NROWS * 32 + 255) / 256, 256>>>();
    koleo_reduce<<<1, 256>>>(out);
}

// round 11
// speedup vs baseline: 12.9995x; 1.0179x over previous
#include <cuda_runtime.h>
#include <cuda_bf16.h>
#include <stdint.h>
#include <math.h>

#define NROWS 8192
#define NDIM  384
#define EPSV  1e-8f

#define BM 128
#define BN 128
#define NB (NROWS / BM)            // 64
#define NTILES (NB * (NB + 1) / 2) // 2080
#define NSEG 148                   // persistent CTAs (one per SM)
#define KC 128                     // k per B chunk
#define NCHUNK (NDIM / KC)         // 3

#define ASB 784                    // A smem row stride bytes (768 + 16)
#define ABYTES (BM * ASB)          // 100352
#define BSB 272                    // B smem row stride bytes (256 + 16)
#define BBUF (BM * BSB)            // 34816
#define RED_OFF (ABYTES + 2 * BBUF)        // 169984
#define SMEM_TOTAL (RED_OFF + 32768)       // 202752

#define DIST_BLOCKS 1024

// Scratch (static device memory; no allocations)
__device__ __align__(16) float g_x[(size_t)NROWS * NDIM];            // fp32 (distances)
__device__ __align__(16) __nv_bfloat16 g_xh[(size_t)NROWS * NDIM];   // bf16 (HMMA)
__device__ unsigned long long g_best[NROWS];                          // packed (val,idx)
__device__ float g_part[DIST_BLOCKS];                                 // per-block partials
__device__ unsigned g_tick;                                           // completion ticket

__device__ __forceinline__ void ldsm_x4(unsigned& r0, unsigned& r1,
                                        unsigned& r2, unsigned& r3,
                                        unsigned addr) {
    asm volatile("ldmatrix.sync.aligned.m8n8.x4.shared.b16 {%0,%1,%2,%3}, [%4];"
                 : "=r"(r0), "=r"(r1), "=r"(r2), "=r"(r3) : "r"(addr));
}
__device__ __forceinline__ void mma16816(float* c, const unsigned* a,
                                         const unsigned* b) {
    asm volatile("mma.sync.aligned.m16n8k16.row.col.f32.bf16.bf16.f32 "
                 "{%0,%1,%2,%3}, {%4,%5,%6,%7}, {%8,%9}, {%0,%1,%2,%3};"
                 : "+f"(c[0]), "+f"(c[1]), "+f"(c[2]), "+f"(c[3])
                 : "r"(a[0]), "r"(a[1]), "r"(a[2]), "r"(a[3]),
                   "r"(b[0]), "r"(b[1]));
}
__device__ __forceinline__ void cp_async16(unsigned dst, const void* src) {
    asm volatile("cp.async.cg.shared.global [%0], [%1], 16;"
                 :: "r"(dst), "l"(src) : "memory");
}
__device__ __forceinline__ void cp_commit() {
    asm volatile("cp.async.commit_group;" ::: "memory");
}
__device__ __forceinline__ void cp_wait1() {
    asm volatile("cp.async.wait_group 1;" ::: "memory");
}
__device__ __forceinline__ void cp_wait0() {
    asm volatile("cp.async.wait_group 0;" ::: "memory");
}
__device__ __forceinline__ unsigned long long pack_best(float v, int idx) {
    unsigned u = __float_as_uint(v);
    u = (u & 0x80000000u) ? ~u : (u | 0x80000000u);
    return ((unsigned long long)u << 32) | (unsigned)(0xFFFFFFFFu - (unsigned)idx);
}
__device__ __forceinline__ void decode_tile(int t, int& bi, int& bj) {
    int b = 0, rem = t;
    while (rem >= NB - b) { rem -= NB - b; b++; }
    bi = b; bj = b + rem;
}

// ---------------------------------------------------------------------------
// Kernel 1: L2 normalize rows (warp/row); resets g_best and ticket.
// ---------------------------------------------------------------------------
__global__ void koleo_normalize(const float* __restrict__ in) {
    int gwarp = (blockIdx.x * blockDim.x + threadIdx.x) >> 5;
    int lane = threadIdx.x & 31;
    if (blockIdx.x == 0 && threadIdx.x == 0) g_tick = 0;
    if (gwarp >= NROWS) return;

    const float4* a4 = (const float4*)(in + (size_t)gwarp * NDIM);
    float4 v[3];
    float ss = 0.0f;
#pragma unroll
    for (int t = 0; t < 3; t++) {
        v[t] = a4[lane + 32 * t];
        ss = fmaf(v[t].x, v[t].x, ss);
        ss = fmaf(v[t].y, v[t].y, ss);
        ss = fmaf(v[t].z, v[t].z, ss);
        ss = fmaf(v[t].w, v[t].w, ss);
    }
#pragma unroll
    for (int o = 16; o > 0; o >>= 1)
        ss += __shfl_xor_sync(0xffffffffu, ss, o);

    float inv = 1.0f / fmaxf(sqrtf(ss), EPSV);

    if (lane == 0) g_best[gwarp] = 0ull;

    float4* o4 = (float4*)(g_x + (size_t)gwarp * NDIM);
    __nv_bfloat162* h2 = (__nv_bfloat162*)(g_xh + (size_t)gwarp * NDIM);
#pragma unroll
    for (int t = 0; t < 3; t++) {
        float4 w;
        w.x = v[t].x * inv; w.y = v[t].y * inv;
        w.z = v[t].z * inv; w.w = v[t].w * inv;
        o4[lane + 32 * t] = w;
        __nv_bfloat162 p0, p1;
        p0.x = __float2bfloat16_rn(w.x); p0.y = __float2bfloat16_rn(w.y);
        p1.x = __float2bfloat16_rn(w.z); p1.y = __float2bfloat16_rn(w.w);
        h2[(lane + 32 * t) * 2 + 0] = p0;
        h2[(lane + 32 * t) * 2 + 1] = p1;
    }
}

// ---------------------------------------------------------------------------
// Kernel 2: persistent upper-triangle Gram tiles (148 CTAs, 14-15 tiles each).
// A block smem-resident across a bi-run; B double-buffered, cross-tile
// chunk-0 prefetch; run-boundary A load hidden under the flush epilogue.
// ---------------------------------------------------------------------------
__global__ void __launch_bounds__(256, 1) koleo_argmax(unsigned long long* __restrict__ best) {
    extern __shared__ __align__(16) unsigned char smraw[];
    const unsigned smb = (unsigned)__cvta_generic_to_shared(smraw);
    const unsigned smA = smb;
    const unsigned smB = smb + ABYTES;

    const int tid = threadIdx.x;
    const int wid = tid >> 5;
    const int lane = tid & 31;
    const int wm = wid >> 2;
    const int wn = wid & 3;
    const int r_in_warp = lane >> 2;
    const int c_in_quad = (lane & 3) * 2;

    const int t_begin = (int)(((long long)blockIdx.x * NTILES) / NSEG);
    const int t_end   = (int)(((long long)(blockIdx.x + 1) * NTILES) / NSEG);

    float* rv = (float*)(smraw + RED_OFF);
    int*   ri = (int*)(smraw + RED_OFF + 8192);
    float* cv = (float*)(smraw + RED_OFF + 16384);
    int*   ci = (int*)(smraw + RED_OFF + 24576);

    const unsigned as_off = (wm * 64 + (lane & 15)) * ASB + (lane >> 4) * 16;
    const unsigned bs_off = (wn * 32 + (lane & 15)) * BSB + (lane >> 4) * 16;

    auto issue_A = [&](int bi) {
#pragma unroll
        for (int i = 0; i < 24; i++) {
            int q = i * 256 + tid;
            int r = q / 48, c = q % 48;
            cp_async16(smA + r * ASB + c * 16,
                       (const void*)(g_xh + (size_t)(bi * BM + r) * NDIM + c * 8));
        }
    };
    auto issue_B = [&](int bj, int chunk, int buf) {
        const unsigned bb = smB + buf * BBUF;
        const size_t kof = (size_t)chunk * KC;
#pragma unroll
        for (int i = 0; i < 8; i++) {
            int q = i * 256 + tid;
            int r = q >> 4, s = q & 15;
            cp_async16(bb + r * BSB + s * 16,
                       (const void*)(g_xh + (size_t)(bj * BM + r) * NDIM + kof + s * 8));
        }
    };

    float rbv[8];
    int   rbx[8];
#pragma unroll
    for (int i = 0; i < 8; i++) { rbv[i] = -2.0f; rbx[i] = 0x7fffffff; }

    int bi, bj;
    decode_tile(t_begin, bi, bj);
    int a_bi = bi;
    issue_A(bi);
    issue_B(bj, 0, 0);
    cp_commit();
    int par = 0;

    for (int t = t_begin; t < t_end; ++t) {
        const bool has_next = (t + 1 < t_end);
        int nbi = -1, nbj = -1;
        if (has_next) decode_tile(t + 1, nbi, nbj);
        const bool diag = (bi == bj);
        const bool boundary = has_next && (nbi != a_bi);

        float acc[4][4][4];
#pragma unroll
        for (int mi = 0; mi < 4; mi++)
#pragma unroll
            for (int ni = 0; ni < 4; ni++)
#pragma unroll
                for (int r = 0; r < 4; r++) acc[mi][ni][r] = 0.0f;

#pragma unroll
        for (int c = 0; c < NCHUNK; c++) {
            bool issued = false;
            if (c < NCHUNK - 1) {
                issue_B(bj, c + 1, par ^ 1); cp_commit(); issued = true;
            } else if (has_next && !boundary) {
                issue_B(nbj, 0, par ^ 1); cp_commit(); issued = true;  // prefetch
            }
            if (issued) cp_wait1(); else cp_wait0();
            __syncthreads();

            const unsigned as_base = smA + as_off;
            const unsigned bs_base = smB + par * BBUF + bs_off;
#pragma unroll
            for (int ksc = 0; ksc < KC / 16; ++ksc) {
                const unsigned akoff = (c * 8 + ksc) * 32;
                const unsigned bkoff = ksc * 32;

                unsigned afr[4][4];
#pragma unroll
                for (int mi = 0; mi < 4; mi++)
                    ldsm_x4(afr[mi][0], afr[mi][1], afr[mi][2], afr[mi][3],
                            as_base + mi * 16 * ASB + akoff);

                unsigned bfr[4][2];
#pragma unroll
                for (int np = 0; np < 2; np++) {
                    unsigned r0, r1, r2, r3;
                    ldsm_x4(r0, r1, r2, r3, bs_base + np * 16 * BSB + bkoff);
                    bfr[np * 2 + 0][0] = r0; bfr[np * 2 + 0][1] = r2;
                    bfr[np * 2 + 1][0] = r1; bfr[np * 2 + 1][1] = r3;
                }

#pragma unroll
                for (int mi = 0; mi < 4; mi++)
#pragma unroll
                    for (int ni = 0; ni < 4; ni++)
                        mma16816(acc[mi][ni], afr[mi], bfr[ni]);
            }
            __syncthreads();
            par ^= 1;
        }

        // Run-boundary: launch next run's A + B chunk-0 NOW so the loads are
        // hidden under the epilogue below. Safe: chunk loop ended with
        // __syncthreads, so all warps are done reading smA.
        if (boundary) {
            issue_A(nbi);
            issue_B(nbj, 0, par);
            cp_commit();
            a_bi = nbi;
        }

        // ===== Epilogue =====
        const bool flush = !has_next || (nbi != bi);

        // Row direction: accumulate in registers (run-long).
#pragma unroll
        for (int mi = 0; mi < 4; mi++) {
#pragma unroll
            for (int h = 0; h < 2; h++) {
                const int six = mi * 2 + h;
                const int gi = bi * BM + wm * 64 + mi * 16 + r_in_warp + 8 * h;
                float bv = rbv[six]; int bx = rbx[six];
#pragma unroll
                for (int ni = 0; ni < 4; ni++) {
#pragma unroll
                    for (int cc = 0; cc < 2; cc++) {
                        float v = acc[mi][ni][h * 2 + cc];
                        int gj = bj * BN + wn * 32 + ni * 8 + c_in_quad + cc;
                        if (gi != gj && (v > bv || (v == bv && gj < bx))) {
                            bv = v; bx = gj;
                        }
                    }
                }
                rbv[six] = bv; rbx[six] = bx;
            }
        }

        // Column candidates to smem (off-diagonal tiles only).
        if (!diag) {
#pragma unroll
            for (int ni = 0; ni < 4; ni++) {
#pragma unroll
                for (int cc = 0; cc < 2; cc++) {
                    const int lc = wn * 32 + ni * 8 + c_in_quad + cc;
                    float bv = -2.0f; int bx = 0x7fffffff;
#pragma unroll
                    for (int mi = 0; mi < 4; mi++) {
#pragma unroll
                        for (int h = 0; h < 2; h++) {
                            float v = acc[mi][ni][h * 2 + cc];
                            int gi = bi * BM + wm * 64 + mi * 16 + r_in_warp + 8 * h;
                            if (v > bv || (v == bv && gi < bx)) { bv = v; bx = gi; }
                        }
                    }
                    cv[lc * 16 + wm * 8 + r_in_warp] = bv;
                    ci[lc * 16 + wm * 8 + r_in_warp] = bx;
                }
            }
        }
        if (flush) {
#pragma unroll
            for (int mi = 0; mi < 4; mi++) {
#pragma unroll
                for (int h = 0; h < 2; h++) {
                    const int lr = wm * 64 + mi * 16 + r_in_warp + 8 * h;
                    rv[lr * 16 + wn * 4 + (lane & 3)] = rbv[mi * 2 + h];
                    ri[lr * 16 + wn * 4 + (lane & 3)] = rbx[mi * 2 + h];
                }
            }
        }

        if (!diag || flush) {
            __syncthreads();
            if (!diag && tid < BM) {
                float bv = -2.0f; int bx = 0x7fffffff;
#pragma unroll
                for (int s = 0; s < 16; s++) {
                    float v = cv[tid * 16 + s];
                    int ix = ci[tid * 16 + s];
                    if (v > bv || (v == bv && ix < bx)) { bv = v; bx = ix; }
                }
                atomicMax(&best[bj * BN + tid], pack_best(bv, bx));
            }
            if (flush && tid >= BM) {
                const int row = tid - BM;
                float bv = -2.0f; int bx = 0x7fffffff;
#pragma unroll
                for (int s = 0; s < 16; s++) {
                    float v = rv[row * 16 + s];
                    int ix = ri[row * 16 + s];
                    if (v > bv || (v == bv && ix < bx)) { bv = v; bx = ix; }
                }
                atomicMax(&best[bi * BM + row], pack_best(bv, bx));
            }
        }
        if (flush) {
#pragma unroll
            for (int i = 0; i < 8; i++) { rbv[i] = -2.0f; rbx[i] = 0x7fffffff; }
        }

        if (has_next) { bi = nbi; bj = nbj; }
    }
}

// ---------------------------------------------------------------------------
// Kernel 3: decode neighbor, log pairwise distance, fused final reduction.
// Warp per row; per-block partial -> last finished block sums (deterministic:
// fixed-order array sum) and writes the loss.
// ---------------------------------------------------------------------------
__global__ void koleo_dist_reduce(float* __restrict__ out) {
    __shared__ float spart[8];
    __shared__ unsigned slast;

    int gwarp = (blockIdx.x * blockDim.x + threadIdx.x) >> 5;
    int wid = threadIdx.x >> 5;
    int lane = threadIdx.x & 31;

    float lg = 0.0f;
    if (gwarp < NROWS) {
        unsigned long long key = g_best[gwarp];
        int bi = (int)(0xFFFFFFFFu - (unsigned)(key & 0xFFFFFFFFull));

        const float4* a4 = (const float4*)(g_x + (size_t)gwarp * NDIM);
        const float4* b4 = (const float4*)(g_x + (size_t)bi * NDIM);
        float ss = 0.0f;
#pragma unroll
        for (int t = 0; t < 3; t++) {
            float4 a = a4[lane + 32 * t];
            float4 b = b4[lane + 32 * t];
            float dx = a.x - b.x + EPSV;
            float dy = a.y - b.y + EPSV;
            float dz = a.z - b.z + EPSV;
            float dw = a.w - b.w + EPSV;
            ss = fmaf(dx, dx, ss);
            ss = fmaf(dy, dy, ss);
            ss = fmaf(dz, dz, ss);
            ss = fmaf(dw, dw, ss);
        }
#pragma unroll
        for (int o = 16; o > 0; o >>= 1)
            ss += __shfl_xor_sync(0xffffffffu, ss, o);
        lg = logf(sqrtf(ss) + EPSV);
    }
    if (lane == 0) spart[wid] = lg;
    __syncthreads();

    if (threadIdx.x == 0) {
        float acc = 0.0f;
#pragma unroll
        for (int w = 0; w < 8; w++) acc += spart[w];
        g_part[blockIdx.x] = acc;
        __threadfence();
        unsigned t = atomicAdd(&g_tick, 1u);
        slast = (t == DIST_BLOCKS - 1) ? 1u : 0u;
    }
    __syncthreads();

    if (slast) {
        // Last block: deterministic fixed-order sum of all partials.
        float acc = 0.0f;
        for (int i = threadIdx.x; i < DIST_BLOCKS; i += 256) acc += g_part[i];
        __shared__ float s[256];
        s[threadIdx.x] = acc;
        __syncthreads();
        for (int w = 128; w > 0; w >>= 1) {
            if (threadIdx.x < w) s[threadIdx.x] += s[threadIdx.x + w];
            __syncthreads();
        }
        if (threadIdx.x == 0) out[0] = -s[0] / (float)NROWS;
    }
}

// ---------------------------------------------------------------------------
extern "C" void kernel_launch(void* const* d_in, const int* in_sizes, int n_in,
                              void* d_out, int out_size) {
    const float* in = (const float*)d_in[0];
    float* out = (float*)d_out;

    koleo_normalize<<<(NROWS * 32 + 255) / 256, 256>>>(in);

    cudaFuncSetAttribute(koleo_argmax, cudaFuncAttributeMaxDynamicSharedMemorySize,
                         SMEM_TOTAL);
    unsigned long long* best = nullptr;
    cudaGetSymbolAddress((void**)&best, g_best);
    koleo_argmax<<<NSEG, 256, SMEM_TOTAL>>>(best);

    koleo_dist_reduce<<<DIST_BLOCKS, 256>>>(out);
}